// round 16
// baseline (speedup 1.0000x reference)
#include <cuda_runtime.h>
#include <cuda_fp16.h>

#define Bz 8
#define Lz 512
#define Dz 128
#define D2 64   // Dz/2 half2 pairs

// ---- scratch (device globals; no allocation allowed) ----
__device__ __half2 g_Qh[Bz*Lz*D2];
__device__ __half2 g_Kh[Bz*Lz*D2];
__device__ float   g_V [Bz*Lz*Dz];
__device__ float   g_P [Bz*Lz*Lz];   // attn probabilities
__device__ __half2 g_w2h[D2];        // combined score weights (half2)
__device__ float   g_b[1];

__device__ __forceinline__ void cp16(unsigned smem, const void* g){
    asm volatile("cp.async.ca.shared.global [%0], [%1], 16;" :: "r"(smem), "l"(g));
}

// ---- projection tile body: Out[n,o] = sum_i X[n,i]*W[o,i] + b[o] ----
// 64n x 64o tile, 256 thr, thread = 4n x 4o. K split in two 64-halves.
// which: 0 -> g_Qh (half2), 1 -> g_Kh (half2), 2 -> g_V (fp32)
__device__ __forceinline__ void proj_tile(
        const float* __restrict__ X, const float* __restrict__ W,
        const float* __restrict__ bias, int which, int n0, int o0,
        float* Ws, float* Xs, int tid){
    int tr = tid >> 4;
    int tc = tid & 15;

    float acc[4][4];
    #pragma unroll
    for (int r = 0; r < 4; r++)
        #pragma unroll
        for (int j = 0; j < 4; j++) acc[r][j] = 0.f;

    #pragma unroll
    for (int kh = 0; kh < 2; kh++){
        __syncthreads();
        for (int idx = tid; idx < 1024; idx += 256){
            int r = idx >> 4, c = idx & 15;
            *(float4*)&Ws[r*68 + c*4] = *(const float4*)&W[(o0+r)*Dz + kh*64 + c*4];
            *(float4*)&Xs[r*68 + c*4] = *(const float4*)&X[(n0+r)*Dz + kh*64 + c*4];
        }
        __syncthreads();
        #pragma unroll 4
        for (int c = 0; c < 16; c++){
            float4 w0 = *(float4*)&Ws[(2*tc   )*68 + c*4];
            float4 w1 = *(float4*)&Ws[(2*tc+ 1)*68 + c*4];
            float4 w2 = *(float4*)&Ws[(2*tc+32)*68 + c*4];
            float4 w3 = *(float4*)&Ws[(2*tc+33)*68 + c*4];
            #pragma unroll
            for (int r = 0; r < 4; r++){
                float4 x = *(float4*)&Xs[(4*tr+r)*68 + c*4];
                acc[r][0] += w0.x*x.x + w0.y*x.y + w0.z*x.z + w0.w*x.w;
                acc[r][1] += w1.x*x.x + w1.y*x.y + w1.z*x.z + w1.w*x.w;
                acc[r][2] += w2.x*x.x + w2.y*x.y + w2.z*x.z + w2.w*x.w;
                acc[r][3] += w3.x*x.x + w3.y*x.y + w3.z*x.z + w3.w*x.w;
            }
        }
    }

    float b0 = bias[o0 + 2*tc],      b1 = bias[o0 + 2*tc + 1];
    float b2 = bias[o0 + 2*tc + 32], b3 = bias[o0 + 2*tc + 33];

    if (which == 2){
        #pragma unroll
        for (int r = 0; r < 4; r++){
            int n = n0 + 4*tr + r;
            *(float2*)&g_V[n*Dz + o0 + 2*tc]      = make_float2(acc[r][0]+b0, acc[r][1]+b1);
            *(float2*)&g_V[n*Dz + o0 + 2*tc + 32] = make_float2(acc[r][2]+b2, acc[r][3]+b3);
        }
    } else {
        __half2* dst = which ? g_Kh : g_Qh;
        int d2a = (o0 >> 1) + tc;
        int d2b = d2a + 16;
        #pragma unroll
        for (int r = 0; r < 4; r++){
            int n = n0 + 4*tr + r;
            dst[n*D2 + d2a] = __floats2half2_rn(acc[r][0]+b0, acc[r][1]+b1);
            dst[n*D2 + d2b] = __floats2half2_rn(acc[r][2]+b2, acc[r][3]+b3);
        }
    }
}

// ---- launch 1: Q-proj + K-proj + prep (1-D grid 257) ----
__global__ void __launch_bounds__(256, 2)
k_qk_prep(const float* __restrict__ Xq, const float* __restrict__ Xk,
          const float* __restrict__ Wq, const float* __restrict__ bq,
          const float* __restrict__ Wk, const float* __restrict__ bk,
          const float* wd, const float* bd, const float* ws,
          const float* bs, const float* wt, const float* bt){
    __shared__ __align__(16) float sm[2*64*68];
    int id = blockIdx.x;
    int tid = threadIdx.x;
    if (id == 256){
        if (tid < D2){
            float base = 0.08838834764831845f; // 1/sqrt(128)
            float wx = base + wd[2*tid]   + ws[2*tid]   + wt[2*tid];
            float wy = base + wd[2*tid+1] + ws[2*tid+1] + wt[2*tid+1];
            g_w2h[tid] = __floats2half2_rn(wx, wy);
        }
        if (tid == 0) g_b[0] = bd[0] + bs[0] + bt[0];
        return;
    }
    int which = id >> 7;                  // 0 = Q, 1 = K
    int rem = id & 127;
    int n0 = (rem & 63) * 64;
    int o0 = (rem >> 6) * 64;
    proj_tile(which ? Xk : Xq, which ? Wk : Wq, which ? bk : bq,
              which, n0, o0, sm, sm + 64*68, tid);
}

// ---- launch 2: V-proj (blocks 0..127, runs first) + scores (128..383) ----
// One wave at occupancy 3 (384 <= 444 resident). Scores CTA = (16 q, b):
// warp w owns q rows 2w,2w+1; lane kl owns k=kl,kl+32 per 64-k tile.
// No K prefetch regs (extra warps hide L2-hit fill latency).
__global__ void __launch_bounds__(256, 3)
k_scores_v(const float* __restrict__ Xv, const float* __restrict__ Wv,
           const float* __restrict__ bv){
    __shared__ __align__(16) float sm[2*64*68];   // 34816B union
    int id = blockIdx.x;
    int tid = threadIdx.x;

    if (id < 128){                        // V projection FIRST (no tail)
        int n0 = (id & 63) * 64;
        int o0 = (id >> 6) * 64;
        proj_tile(Xv, Wv, bv, 2, n0, o0, sm, sm + 64*68, tid);
        return;
    }

    __half2* Ksh = (__half2*)sm;                  // [D2][64] 16KB
    __half2* Qsh = (__half2*)(sm + 4096);         // [16][D2] 4KB
    __half2* swh = (__half2*)(sm + 4096 + 1024);  // [D2] 256B

    int sid = id - 128;
    int b   = sid >> 5;
    int q0  = (sid & 31) * 16;
    int kl  = tid & 31, w = tid >> 5;

    for (int idx = tid; idx < 16*D2; idx += 256){
        int q = idx >> 6, d2 = idx & 63;
        Qsh[q*D2 + d2] = g_Qh[(b*Lz + q0 + q)*D2 + d2];
    }
    if (tid < D2) swh[tid] = g_w2h[tid];
    float ball = g_b[0];

    const __half2* Kg = &g_Kh[(b*Lz)*D2];
    int frow = tid >> 4, fc4 = tid & 15;

    float va[16], vb[16];

    #pragma unroll
    for (int kt = 0; kt < 8; kt++){
        __syncthreads();
        {   // fill K tile: load all 4 float4 first, then scatter-store
            float4 t[4];
            #pragma unroll
            for (int i = 0; i < 4; i++)
                t[i] = *(const float4*)&Kg[(kt*64 + frow + i*16)*D2 + fc4*4];
            #pragma unroll
            for (int i = 0; i < 4; i++){
                int r = frow + i*16;
                const __half2* h = (const __half2*)&t[i];
                #pragma unroll
                for (int j = 0; j < 4; j++){
                    int d2 = fc4*4 + j;
                    Ksh[d2*64 + (r ^ d2)] = h[j];
                }
            }
        }
        __syncthreads();

        float fa0 = 0.f, fb0 = 0.f, fa1 = 0.f, fb1 = 0.f;
        #pragma unroll
        for (int g = 0; g < 8; g++){
            __half2 z = __floats2half2_rn(0.f, 0.f);
            __half2 ha0 = z, hb0 = z, ha1 = z, hb1 = z;
            #pragma unroll
            for (int u = 0; u < 8; u++){
                int d2 = g*8 + u;
                __half2 qa = Qsh[(2*w  )*D2 + d2];
                __half2 qb = Qsh[(2*w+1)*D2 + d2];
                __half2 w2 = swh[d2];
                __half2 ka = Ksh[d2*64 + (kl ^ d2)];
                __half2 kb = Ksh[d2*64 + ((kl + 32) ^ d2)];
                __half2 s0 = __hadd2(qa, ka);
                __half2 s1 = __hadd2(qa, kb);
                __half2 s2 = __hadd2(qb, ka);
                __half2 s3 = __hadd2(qb, kb);
                unsigned t0, t1, t2, t3;
                asm("tanh.approx.f16x2 %0, %1;" : "=r"(t0) : "r"(*(unsigned*)&s0));
                asm("tanh.approx.f16x2 %0, %1;" : "=r"(t1) : "r"(*(unsigned*)&s1));
                asm("tanh.approx.f16x2 %0, %1;" : "=r"(t2) : "r"(*(unsigned*)&s2));
                asm("tanh.approx.f16x2 %0, %1;" : "=r"(t3) : "r"(*(unsigned*)&s3));
                ha0 = __hfma2(w2, *(__half2*)&t0, ha0);
                hb0 = __hfma2(w2, *(__half2*)&t1, hb0);
                ha1 = __hfma2(w2, *(__half2*)&t2, ha1);
                hb1 = __hfma2(w2, *(__half2*)&t3, hb1);
            }
            float2 x0 = __half22float2(ha0);
            float2 x1 = __half22float2(hb0);
            float2 x2 = __half22float2(ha1);
            float2 x3 = __half22float2(hb1);
            fa0 += x0.x + x0.y;
            fb0 += x1.x + x1.y;
            fa1 += x2.x + x2.y;
            fb1 += x3.x + x3.y;
        }
        va[2*kt] = fa0 + ball; va[2*kt+1] = fb0 + ball;
        vb[2*kt] = fa1 + ball; vb[2*kt+1] = fb1 + ball;
    }

    float ma = -1e30f, mb = -1e30f;
    #pragma unroll
    for (int j = 0; j < 16; j++){ ma = fmaxf(ma, va[j]); mb = fmaxf(mb, vb[j]); }
    #pragma unroll
    for (int s = 16; s; s >>= 1){
        ma = fmaxf(ma, __shfl_xor_sync(~0u, ma, s));
        mb = fmaxf(mb, __shfl_xor_sync(~0u, mb, s));
    }
    float sa = 0.f, sb = 0.f;
    #pragma unroll
    for (int j = 0; j < 16; j++){
        va[j] = __expf(va[j] - ma); sa += va[j];
        vb[j] = __expf(vb[j] - mb); sb += vb[j];
    }
    #pragma unroll
    for (int s = 16; s; s >>= 1){
        sa += __shfl_xor_sync(~0u, sa, s);
        sb += __shfl_xor_sync(~0u, sb, s);
    }
    float ia = 1.f / sa, ib = 1.f / sb;
    float* da = &g_P[(b*Lz + q0 + 2*w    )*Lz];
    float* db = &g_P[(b*Lz + q0 + 2*w + 1)*Lz];
    #pragma unroll
    for (int kt = 0; kt < 8; kt++){
        da[kt*64 + kl]      = va[2*kt]   * ia;
        da[kt*64 + 32 + kl] = va[2*kt+1] * ia;
        db[kt*64 + kl]      = vb[2*kt]   * ib;
        db[kt*64 + 32 + kl] = vb[2*kt+1] * ib;
    }
}

// ---- launch 3: out[b,q,:] = sum_k attn[b,q,k] * V[b,k,:] ---- (unchanged)
__global__ void k_av(float* __restrict__ Out){
    __shared__ __align__(16) float Vs[2][32][Dz];   // 2 x 16KB
    __shared__ __align__(16) float aP[2][32][32];   // 2 x 4KB
    int b  = blockIdx.y;
    int q0 = blockIdx.x * 32;
    int tid = threadIdx.x;
    int lane = tid & 31, w = tid >> 5;
    int qb = w * 4;

    const float* Vg = &g_V[(b*Lz)*Dz];
    const float* Pg = &g_P[(b*Lz + q0)*Lz];

    int vrow0 = tid >> 5, vcol = (tid & 31) * 4;
    int prow = tid >> 3, pcol = (tid & 7) * 4;

    unsigned sV0 = (unsigned)__cvta_generic_to_shared(&Vs[0][0][0]) + tid*16u;
    unsigned sV1 = (unsigned)__cvta_generic_to_shared(&Vs[1][0][0]) + tid*16u;
    unsigned sA0 = (unsigned)__cvta_generic_to_shared(&aP[0][prow][pcol]);
    unsigned sA1 = (unsigned)__cvta_generic_to_shared(&aP[1][prow][pcol]);

    {
        #pragma unroll
        for (int i = 0; i < 4; i++)
            cp16(sV0 + i*4096u, &Vg[(vrow0 + i*8)*Dz + vcol]);
        cp16(sA0, &Pg[prow*Lz + pcol]);
        asm volatile("cp.async.commit_group;");
    }

    float4 acc0 = make_float4(0.f,0.f,0.f,0.f);
    float4 acc1 = acc0, acc2 = acc0, acc3 = acc0;

    for (int kt = 0; kt < 16; kt++){
        int buf = kt & 1;
        if (kt + 1 < 16){
            int k0 = (kt + 1) * 32;
            unsigned sV = buf ? sV0 : sV1;
            unsigned sA = buf ? sA0 : sA1;
            #pragma unroll
            for (int i = 0; i < 4; i++)
                cp16(sV + i*4096u, &Vg[(k0 + vrow0 + i*8)*Dz + vcol]);
            cp16(sA, &Pg[prow*Lz + k0 + pcol]);
            asm volatile("cp.async.commit_group;");
            asm volatile("cp.async.wait_group 1;");
        } else {
            asm volatile("cp.async.wait_group 0;");
        }
        __syncthreads();

        #pragma unroll 8
        for (int j = 0; j < 32; j++){
            float4 v = *(const float4*)&Vs[buf][j][lane*4];
            float p0 = aP[buf][qb+0][j];
            float p1 = aP[buf][qb+1][j];
            float p2 = aP[buf][qb+2][j];
            float p3 = aP[buf][qb+3][j];
            acc0.x += p0*v.x; acc0.y += p0*v.y; acc0.z += p0*v.z; acc0.w += p0*v.w;
            acc1.x += p1*v.x; acc1.y += p1*v.y; acc1.z += p1*v.z; acc1.w += p1*v.w;
            acc2.x += p2*v.x; acc2.y += p2*v.y; acc2.z += p2*v.z; acc2.w += p2*v.w;
            acc3.x += p3*v.x; acc3.y += p3*v.y; acc3.z += p3*v.z; acc3.w += p3*v.w;
        }
        __syncthreads();
    }
    *(float4*)&Out[(b*Lz + q0 + qb + 0)*Dz + lane*4] = acc0;
    *(float4*)&Out[(b*Lz + q0 + qb + 1)*Dz + lane*4] = acc1;
    *(float4*)&Out[(b*Lz + q0 + qb + 2)*Dz + lane*4] = acc2;
    *(float4*)&Out[(b*Lz + q0 + qb + 3)*Dz + lane*4] = acc3;
}

extern "C" void kernel_launch(void* const* d_in, const int* in_sizes, int n_in,
                              void* d_out, int out_size){
    const float* query = (const float*)d_in[0];
    const float* key_  = (const float*)d_in[1];
    const float* value = (const float*)d_in[2];
    const float* Wq = (const float*)d_in[3];
    const float* bq = (const float*)d_in[4];
    const float* Wk = (const float*)d_in[5];
    const float* bk = (const float*)d_in[6];
    const float* Wv = (const float*)d_in[7];
    const float* bv = (const float*)d_in[8];
    const float* wd = (const float*)d_in[9];
    const float* bd = (const float*)d_in[10];
    const float* ws = (const float*)d_in[11];
    const float* bs = (const float*)d_in[12];
    const float* wt = (const float*)d_in[13];
    const float* bt = (const float*)d_in[14];
    float* out = (float*)d_out;

    k_qk_prep<<<257, 256>>>(query, key_, Wq, bq, Wk, bk,
                            wd, bd, ws, bs, wt, bt);
    k_scores_v<<<384, 256>>>(value, Wv, bv);
    k_av<<<dim3(Lz/32, Bz), 256>>>(out);
}